// round 4
// baseline (speedup 1.0000x reference)
#include <cuda_runtime.h>
#include <cuda_bf16.h>
#include <cstdint>

#define NG 8
#define NE 8192
#define NN 512
#define NP1 513
#define HH 32
#define PLANE (513*513)

// ---------------------------------------------------------------------------
// helpers
// ---------------------------------------------------------------------------
__device__ __forceinline__ unsigned packbf(float lo, float hi) {
    __nv_bfloat162 t = __floats2bfloat162_rn(lo, hi);
    return *reinterpret_cast<unsigned*>(&t);
}

__device__ __forceinline__ void mma_bf16(float* c, const unsigned* a, const unsigned* b) {
    asm volatile(
        "mma.sync.aligned.m16n8k16.row.col.f32.bf16.bf16.f32 "
        "{%0,%1,%2,%3}, {%4,%5,%6,%7}, {%8,%9}, {%0,%1,%2,%3};\n"
        : "+f"(c[0]), "+f"(c[1]), "+f"(c[2]), "+f"(c[3])
        : "r"(a[0]), "r"(a[1]), "r"(a[2]), "r"(a[3]), "r"(b[0]), "r"(b[1]));
}

// Build layer-1 A fragment (16 points x 16 k) from global fp32 rows of 28.
// kstep s: cols s*16 .. s*16+15 (cols >= 28 are zero padding).
__device__ __forceinline__ void loadA28(unsigned* A, const float* p, int s, int qid, int tq) {
    const int k0 = s * 16 + tq * 2;
    float2 x0 = *(const float2*)(p + qid * 28 + k0);
    float2 x1 = *(const float2*)(p + (qid + 8) * 28 + k0);
    float2 x2 = make_float2(0.f, 0.f);
    float2 x3 = make_float2(0.f, 0.f);
    if (k0 + 8 < 28) {
        x2 = *(const float2*)(p + qid * 28 + k0 + 8);
        x3 = *(const float2*)(p + (qid + 8) * 28 + k0 + 8);
    }
    A[0] = packbf(x0.x, x0.y);
    A[1] = packbf(x1.x, x1.y);
    A[2] = packbf(x2.x, x2.y);
    A[3] = packbf(x3.x, x3.y);
}

// relu(hidden) -> layer2 accumulate into c2 (C-frag layout == A-frag layout)
__device__ __forceinline__ void layer2(const float hh[4][4], float c2[4][4],
                                       const unsigned bf2[2][4][2]) {
#pragma unroll
    for (int s = 0; s < 2; s++) {
        unsigned A[4];
        A[0] = packbf(fmaxf(hh[2*s][0], 0.f), fmaxf(hh[2*s][1], 0.f));
        A[1] = packbf(fmaxf(hh[2*s][2], 0.f), fmaxf(hh[2*s][3], 0.f));
        A[2] = packbf(fmaxf(hh[2*s+1][0], 0.f), fmaxf(hh[2*s+1][1], 0.f));
        A[3] = packbf(fmaxf(hh[2*s+1][2], 0.f), fmaxf(hh[2*s+1][3], 0.f));
#pragma unroll
        for (int n = 0; n < 4; n++) mma_bf16(c2[n], A, bf2[s][n]);
    }
}

// ---------------------------------------------------------------------------
// Kernel A: interior fill  out[g,h,i,j] for i,j in [1,512]
// block = 256 threads (8 warps) handles one (g, i) row; each warp 4 tiles of
// 16 consecutive j points. MLPs via bf16 mma.sync m16n8k16.
// ---------------------------------------------------------------------------
__global__ __launch_bounds__(256, 1) void interior_kernel(
    const float* __restrict__ attn_bias,
    const float* __restrict__ angle,
    const float* __restrict__ dists,
    const float* __restrict__ ang_w1, const float* __restrict__ ang_b1,
    const float* __restrict__ ang_w2, const float* __restrict__ ang_b2,
    const float* __restrict__ md_w1,  const float* __restrict__ md_b1,
    const float* __restrict__ md_w2,  const float* __restrict__ md_b2,
    float* __restrict__ out)
{
    __shared__ float sw[4][1024];               // w1a (pad32x32), w1d, w2a, w2d
    __shared__ float sb1a[32], sb1d[32], sb2[32];

    const int tid = threadIdx.x;
    for (int idx = tid; idx < 1024; idx += 256) {
        sw[0][idx] = (idx < 896) ? ang_w1[idx] : 0.f;   // rows 28..31 zero pad
        sw[1][idx] = (idx < 896) ? md_w1[idx]  : 0.f;
        sw[2][idx] = ang_w2[idx];
        sw[3][idx] = md_w2[idx];
    }
    if (tid < 32) {
        sb1a[tid] = ang_b1[tid];
        sb1d[tid] = md_b1[tid];
        sb2[tid]  = ang_b2[tid] + md_b2[tid];
    }
    __syncthreads();

    const int lane = tid & 31;
    const int warp = tid >> 5;
    const int qid  = lane >> 2;   // 0..7
    const int tq   = lane & 3;    // 0..3

    // B fragments in registers: [matrix][kstep][ntile][2]
    unsigned bf[4][2][4][2];
#pragma unroll
    for (int m = 0; m < 4; m++)
#pragma unroll
        for (int s = 0; s < 2; s++)
#pragma unroll
            for (int n = 0; n < 4; n++) {
                const int r0 = s * 16 + tq * 2;
                const int c  = n * 8 + qid;
                bf[m][s][n][0] = packbf(sw[m][r0 * 32 + c],       sw[m][(r0 + 1) * 32 + c]);
                bf[m][s][n][1] = packbf(sw[m][(r0 + 8) * 32 + c], sw[m][(r0 + 9) * 32 + c]);
            }

    float b1a_lo[4], b1a_hi[4], b1d_lo[4], b1d_hi[4], b2_lo[4], b2_hi[4];
#pragma unroll
    for (int n = 0; n < 4; n++) {
        b1a_lo[n] = sb1a[n * 8 + tq * 2]; b1a_hi[n] = sb1a[n * 8 + tq * 2 + 1];
        b1d_lo[n] = sb1d[n * 8 + tq * 2]; b1d_hi[n] = sb1d[n * 8 + tq * 2 + 1];
        b2_lo[n]  = sb2 [n * 8 + tq * 2]; b2_hi[n]  = sb2 [n * 8 + tq * 2 + 1];
    }

    const int bid = blockIdx.x;
    const int g = bid >> 9;           // / 512
    const int i = (bid & 511) + 1;    // out row 1..512
    const size_t rowp = (size_t)(g * NN + (i - 1)) * NN * 28;
    const float* angRow  = angle + rowp;
    const float* dstRow  = dists + rowp;
    const float* attnRow = attn_bias + ((size_t)g * NP1 + i) * NP1;
    float* outRow = out + (size_t)g * HH * PLANE + (size_t)i * NP1;

#pragma unroll 1
    for (int t = warp; t < 32; t += 8) {
        const int j0 = t * 16;
        const float* ap = angRow + (size_t)j0 * 28;
        const float* dp = dstRow + (size_t)j0 * 28;

        float c2[4][4];
#pragma unroll
        for (int n = 0; n < 4; n++) {
            c2[n][0] = b2_lo[n]; c2[n][1] = b2_hi[n];
            c2[n][2] = b2_lo[n]; c2[n][3] = b2_hi[n];
        }

        float hh[4][4];
        // ---- MLP(angle) ----
#pragma unroll
        for (int n = 0; n < 4; n++) {
            hh[n][0] = b1a_lo[n]; hh[n][1] = b1a_hi[n];
            hh[n][2] = b1a_lo[n]; hh[n][3] = b1a_hi[n];
        }
#pragma unroll
        for (int s = 0; s < 2; s++) {
            unsigned A[4];
            loadA28(A, ap, s, qid, tq);
#pragma unroll
            for (int n = 0; n < 4; n++) mma_bf16(hh[n], A, bf[0][s][n]);
        }
        layer2(hh, c2, bf[2]);

        // ---- MLP(dists) ----
#pragma unroll
        for (int n = 0; n < 4; n++) {
            hh[n][0] = b1d_lo[n]; hh[n][1] = b1d_hi[n];
            hh[n][2] = b1d_lo[n]; hh[n][3] = b1d_hi[n];
        }
#pragma unroll
        for (int s = 0; s < 2; s++) {
            unsigned A[4];
            loadA28(A, dp, s, qid, tq);
#pragma unroll
            for (int n = 0; n < 4; n++) mma_bf16(hh[n], A, bf[1][s][n]);
        }
        layer2(hh, c2, bf[3]);

        // ---- add attn_bias base, store ----
        const float at_lo = attnRow[j0 + 1 + qid];
        const float at_hi = attnRow[j0 + 9 + qid];
#pragma unroll
        for (int n = 0; n < 4; n++) {
            float* o = outRow + (size_t)(n * 8 + tq * 2) * PLANE;
            o[j0 + 1 + qid]         = c2[n][0] + at_lo;
            o[PLANE + j0 + 1 + qid] = c2[n][1] + at_lo;
            o[j0 + 9 + qid]         = c2[n][2] + at_hi;
            o[PLANE + j0 + 9 + qid] = c2[n][3] + at_hi;
        }
    }
}

// ---------------------------------------------------------------------------
// Kernel B: border fill (row 0 and column 0): attn + virt
// ---------------------------------------------------------------------------
__global__ __launch_bounds__(256) void border_kernel(
    const float* __restrict__ attn_bias,
    const float* __restrict__ virt,
    float* __restrict__ out)
{
    const int idx = blockIdx.x * 256 + threadIdx.x;
    const int total = NG * HH * 1025;
    if (idx >= total) return;
    const int pos = idx % 1025;
    const int gh  = idx / 1025;
    const int h = gh & 31;
    const int g = gh >> 5;
    const float v = virt[h];
    float* ob = out + ((size_t)(g * HH + h)) * PLANE;
    const float* ab = attn_bias + (size_t)g * PLANE;
    if (pos < NP1) {
        ob[pos] = ab[pos] + v;                        // row 0, all j
    } else {
        const int i = pos - 512;                      // 1..512
        ob[(size_t)i * NP1] = ab[(size_t)i * NP1] + v; // col 0
    }
}

// ---------------------------------------------------------------------------
// Kernel C: edge scatter-add. One warp per edge, lane = head h.
// edge_mask is a jax bool materialized as int32 by the harness.
// ---------------------------------------------------------------------------
__global__ __launch_bounds__(256) void edge_kernel(
    const float* __restrict__ edge_feat,
    const int*   __restrict__ edge_index,
    const int*   __restrict__ edge_mask,
    const int*   __restrict__ num_ligand_atoms,
    const float* __restrict__ struct_emb,
    const float* __restrict__ plip_lig,
    const float* __restrict__ plip_prot,
    const float* __restrict__ plip_inter,
    const float* __restrict__ dist_w1, const float* __restrict__ dist_b1,
    const float* __restrict__ dist_w2, const float* __restrict__ dist_b2,
    float* __restrict__ out)
{
    __shared__ float s_w2[1024];
    __shared__ float s_w1[32], s_b1[32], s_b2[32];
    const int tid = threadIdx.x;
    for (int idx = tid; idx < 1024; idx += 256) s_w2[idx] = dist_w2[idx];
    if (tid < 32) {
        s_w1[tid] = dist_w1[tid];
        s_b1[tid] = dist_b1[tid];
        s_b2[tid] = dist_b2[tid];
    }
    __syncthreads();

    const int warp = tid >> 5;
    const int lane = tid & 31;
    const int eid = blockIdx.x * 8 + warp;     // 0 .. G*E-1 (grid exact)
    if (eid >= NG * NE) return;
    if (edge_mask[eid] == 0) return;           // masked edges contribute 0

    const int g = eid >> 13;                   // / 8192
    const int e = eid & (NE - 1);

    const float4 ef = reinterpret_cast<const float4*>(edge_feat)[eid];
    const int t0 = (int)ef.x;
    const int t1 = (int)ef.y;
    const int t2 = (int)ef.z;
    const float d = ef.w;

    const int src = edge_index[(size_t)g * 2 * NE + e];
    const int tgt = edge_index[(size_t)g * 2 * NE + NE + e];
    int nl = num_ligand_atoms[g];
    nl = nl > 1 ? nl : 1;
    const bool sl = (src > 0) && (src < nl);
    const bool tl = (tgt > 0) && (tgt < nl);

    // distance MLP: scalar -> 32 -> 32 (lane = output h)
    const float hid = fmaxf(fmaf(d, s_w1[lane], s_b1[lane]), 0.f);
    float y = s_b2[lane];
#pragma unroll
    for (int m = 0; m < 32; m++)
        y = fmaf(__shfl_sync(0xffffffffu, hid, m), s_w2[m * 32 + lane], y);

    float sel = 0.f;
    if (t0 <= 1) {
        int si = t0 * 4 + t1 * 2 + t2;
        si = si < 0 ? 0 : (si > 19 ? 19 : si);
        sel = struct_emb[si * 32 + lane];
    } else if (t0 == 5) {
        int pi = t1 < 0 ? 0 : (t1 > 14 ? 14 : t1);
        const float* tab = (sl && tl) ? plip_lig : ((!sl && !tl) ? plip_prot : plip_inter);
        sel = tab[pi * 32 + lane];
    }

    atomicAdd(out + (((size_t)(g * HH + lane)) * NP1 + (src + 1)) * NP1 + (tgt + 1), y + sel);
}

// ---------------------------------------------------------------------------
extern "C" void kernel_launch(void* const* d_in, const int* in_sizes, int n_in,
                              void* d_out, int out_size) {
    const float* edge_feat  = (const float*)d_in[0];
    const int*   edge_index = (const int*)d_in[1];
    const int*   edge_mask  = (const int*)d_in[2];
    const int*   num_lig    = (const int*)d_in[3];
    const float* attn_bias  = (const float*)d_in[4];
    const float* angle      = (const float*)d_in[5];
    const float* dists      = (const float*)d_in[6];
    // d_in[7] node_feat unused (shape only in reference)
    const float* struct_emb = (const float*)d_in[8];
    const float* plip_lig   = (const float*)d_in[9];
    const float* plip_prot  = (const float*)d_in[10];
    const float* plip_inter = (const float*)d_in[11];
    const float* dist_w1 = (const float*)d_in[12];
    const float* dist_b1 = (const float*)d_in[13];
    const float* dist_w2 = (const float*)d_in[14];
    const float* dist_b2 = (const float*)d_in[15];
    const float* ang_w1  = (const float*)d_in[16];
    const float* ang_b1  = (const float*)d_in[17];
    const float* ang_w2  = (const float*)d_in[18];
    const float* ang_b2  = (const float*)d_in[19];
    const float* md_w1   = (const float*)d_in[20];
    const float* md_b1   = (const float*)d_in[21];
    const float* md_w2   = (const float*)d_in[22];
    const float* md_b2   = (const float*)d_in[23];
    const float* virt    = (const float*)d_in[24];
    float* out = (float*)d_out;

    // interior + border overwrite the whole output (disjoint regions),
    // then edge kernel atomically adds on top (stream-ordered).
    interior_kernel<<<NG * NN, 256>>>(attn_bias, angle, dists,
                                      ang_w1, ang_b1, ang_w2, ang_b2,
                                      md_w1, md_b1, md_w2, md_b2, out);
    border_kernel<<<(NG * HH * 1025 + 255) / 256, 256>>>(attn_bias, virt, out);
    edge_kernel<<<NG * NE / 8, 256>>>(edge_feat, edge_index, edge_mask, num_lig,
                                      struct_emb, plip_lig, plip_prot, plip_inter,
                                      dist_w1, dist_b1, dist_w2, dist_b2, out);
}

// round 5
// speedup vs baseline: 1.1521x; 1.1521x over previous
#include <cuda_runtime.h>
#include <cuda_bf16.h>
#include <cstdint>

#define NG 8
#define NE 8192
#define NN 512
#define NP1 513
#define HH 32
#define PLANE (513*513)

// ---------------------------------------------------------------------------
// helpers
// ---------------------------------------------------------------------------
__device__ __forceinline__ unsigned packbf(float lo, float hi) {
    __nv_bfloat162 t = __floats2bfloat162_rn(lo, hi);
    return *reinterpret_cast<unsigned*>(&t);
}
__device__ __forceinline__ unsigned packbf2(float2 v) { return packbf(v.x, v.y); }

__device__ __forceinline__ void mma_bf16(float* c, const unsigned* a, const unsigned* b) {
    asm volatile(
        "mma.sync.aligned.m16n8k16.row.col.f32.bf16.bf16.f32 "
        "{%0,%1,%2,%3}, {%4,%5,%6,%7}, {%8,%9}, {%0,%1,%2,%3};\n"
        : "+f"(c[0]), "+f"(c[1]), "+f"(c[2]), "+f"(c[3])
        : "r"(a[0]), "r"(a[1]), "r"(a[2]), "r"(a[3]), "r"(b[0]), "r"(b[1]));
}

// relu(hidden) -> layer2 accumulate into c2 (C-frag layout == A-frag layout)
__device__ __forceinline__ void layer2(const float hh[4][4], float c2[4][4],
                                       const unsigned bf2w[2][4][2]) {
#pragma unroll
    for (int s = 0; s < 2; s++) {
        unsigned A[4];
        A[0] = packbf(fmaxf(hh[2*s][0], 0.f), fmaxf(hh[2*s][1], 0.f));
        A[1] = packbf(fmaxf(hh[2*s][2], 0.f), fmaxf(hh[2*s][3], 0.f));
        A[2] = packbf(fmaxf(hh[2*s+1][0], 0.f), fmaxf(hh[2*s+1][1], 0.f));
        A[3] = packbf(fmaxf(hh[2*s+1][2], 0.f), fmaxf(hh[2*s+1][3], 0.f));
#pragma unroll
        for (int n = 0; n < 4; n++) mma_bf16(c2[n], A, bf2w[s][n]);
    }
}

// Per-tile prefetched inputs: 8 float2 for angle, 8 for dists, 2 attn scalars.
struct Tile {
    float2 a[8];
    float2 d[8];
    float at0, at1;
};

// Issue all global loads for one 16-point tile (no consumption here — this is
// the software-pipeline fill stage; loads stay in flight during compute).
__device__ __forceinline__ void prefetch_tile(Tile& T,
                                              const float* __restrict__ ap,
                                              const float* __restrict__ dp,
                                              const float* __restrict__ attnRow,
                                              int j0, int qid, int tq) {
    const int r0 = qid * 28;
    const int r1 = (qid + 8) * 28;
    const int k0 = tq * 2;        // s=0 cols, always in range (k0+8 <= 14)
    const int k1 = 16 + tq * 2;   // s=1 cols, k1 <= 22; k1+8 valid only tq<2
    T.a[0] = __ldcs((const float2*)(ap + r0 + k0));
    T.a[1] = __ldcs((const float2*)(ap + r1 + k0));
    T.a[2] = __ldcs((const float2*)(ap + r0 + k0 + 8));
    T.a[3] = __ldcs((const float2*)(ap + r1 + k0 + 8));
    T.a[4] = __ldcs((const float2*)(ap + r0 + k1));
    T.a[5] = __ldcs((const float2*)(ap + r1 + k1));
    T.d[0] = __ldcs((const float2*)(dp + r0 + k0));
    T.d[1] = __ldcs((const float2*)(dp + r1 + k0));
    T.d[2] = __ldcs((const float2*)(dp + r0 + k0 + 8));
    T.d[3] = __ldcs((const float2*)(dp + r1 + k0 + 8));
    T.d[4] = __ldcs((const float2*)(dp + r0 + k1));
    T.d[5] = __ldcs((const float2*)(dp + r1 + k1));
    if (k1 + 8 < 28) {
        T.a[6] = __ldcs((const float2*)(ap + r0 + k1 + 8));
        T.a[7] = __ldcs((const float2*)(ap + r1 + k1 + 8));
        T.d[6] = __ldcs((const float2*)(dp + r0 + k1 + 8));
        T.d[7] = __ldcs((const float2*)(dp + r1 + k1 + 8));
    } else {
        T.a[6] = T.a[7] = make_float2(0.f, 0.f);
        T.d[6] = T.d[7] = make_float2(0.f, 0.f);
    }
    T.at0 = __ldg(attnRow + j0 + 1 + qid);
    T.at1 = __ldg(attnRow + j0 + 9 + qid);
}

// ---------------------------------------------------------------------------
// Kernel A: interior fill  out[g,h,i,j] for i,j in [1,512]
// block = 256 threads (8 warps) per (g,i) row; each warp 4 tiles of 16 j's.
// Software-pipelined: tile t+1 inputs prefetched into registers during tile
// t's mma/store phase.
// ---------------------------------------------------------------------------
__global__ __launch_bounds__(256, 1) void interior_kernel(
    const float* __restrict__ attn_bias,
    const float* __restrict__ angle,
    const float* __restrict__ dists,
    const float* __restrict__ ang_w1, const float* __restrict__ ang_b1,
    const float* __restrict__ ang_w2, const float* __restrict__ ang_b2,
    const float* __restrict__ md_w1,  const float* __restrict__ md_b1,
    const float* __restrict__ md_w2,  const float* __restrict__ md_b2,
    float* __restrict__ out)
{
    __shared__ float sw[4][1024];               // w1a (pad32x32), w1d, w2a, w2d
    __shared__ float sb1a[32], sb1d[32], sb2[32];

    const int tid = threadIdx.x;
    for (int idx = tid; idx < 1024; idx += 256) {
        sw[0][idx] = (idx < 896) ? ang_w1[idx] : 0.f;   // rows 28..31 zero pad
        sw[1][idx] = (idx < 896) ? md_w1[idx]  : 0.f;
        sw[2][idx] = ang_w2[idx];
        sw[3][idx] = md_w2[idx];
    }
    if (tid < 32) {
        sb1a[tid] = ang_b1[tid];
        sb1d[tid] = md_b1[tid];
        sb2[tid]  = ang_b2[tid] + md_b2[tid];
    }
    __syncthreads();

    const int lane = tid & 31;
    const int warp = tid >> 5;
    const int qid  = lane >> 2;   // 0..7
    const int tq   = lane & 3;    // 0..3

    // B fragments in registers: [matrix][kstep][ntile][2]
    unsigned bf[4][2][4][2];
#pragma unroll
    for (int m = 0; m < 4; m++)
#pragma unroll
        for (int s = 0; s < 2; s++)
#pragma unroll
            for (int n = 0; n < 4; n++) {
                const int r0 = s * 16 + tq * 2;
                const int c  = n * 8 + qid;
                bf[m][s][n][0] = packbf(sw[m][r0 * 32 + c],       sw[m][(r0 + 1) * 32 + c]);
                bf[m][s][n][1] = packbf(sw[m][(r0 + 8) * 32 + c], sw[m][(r0 + 9) * 32 + c]);
            }

    float b1a_lo[4], b1a_hi[4], b1d_lo[4], b1d_hi[4], b2_lo[4], b2_hi[4];
#pragma unroll
    for (int n = 0; n < 4; n++) {
        b1a_lo[n] = sb1a[n * 8 + tq * 2]; b1a_hi[n] = sb1a[n * 8 + tq * 2 + 1];
        b1d_lo[n] = sb1d[n * 8 + tq * 2]; b1d_hi[n] = sb1d[n * 8 + tq * 2 + 1];
        b2_lo[n]  = sb2 [n * 8 + tq * 2]; b2_hi[n]  = sb2 [n * 8 + tq * 2 + 1];
    }

    const int bid = blockIdx.x;
    const int g = bid >> 9;           // / 512
    const int i = (bid & 511) + 1;    // out row 1..512
    const size_t rowp = (size_t)(g * NN + (i - 1)) * NN * 28;
    const float* angRow  = angle + rowp;
    const float* dstRow  = dists + rowp;
    const float* attnRow = attn_bias + ((size_t)g * NP1 + i) * NP1;
    float* outRow = out + (size_t)g * HH * PLANE + (size_t)i * NP1;

    Tile T[2];
    prefetch_tile(T[0], angRow + (size_t)(warp * 16) * 28,
                        dstRow + (size_t)(warp * 16) * 28, attnRow,
                        warp * 16, qid, tq);

#pragma unroll
    for (int it = 0; it < 4; it++) {
        const int cur = it & 1;
        const int t  = warp + it * 8;
        const int j0 = t * 16;

        if (it < 3) {
            const int jn = (t + 8) * 16;
            prefetch_tile(T[cur ^ 1], angRow + (size_t)jn * 28,
                                      dstRow + (size_t)jn * 28, attnRow,
                                      jn, qid, tq);
        }

        const Tile& C = T[cur];

        float c2[4][4];
#pragma unroll
        for (int n = 0; n < 4; n++) {
            c2[n][0] = b2_lo[n]; c2[n][1] = b2_hi[n];
            c2[n][2] = b2_lo[n]; c2[n][3] = b2_hi[n];
        }

        float hh[4][4];
        // ---- MLP(angle) ----
#pragma unroll
        for (int n = 0; n < 4; n++) {
            hh[n][0] = b1a_lo[n]; hh[n][1] = b1a_hi[n];
            hh[n][2] = b1a_lo[n]; hh[n][3] = b1a_hi[n];
        }
        {
            unsigned A[4];
            A[0] = packbf2(C.a[0]); A[1] = packbf2(C.a[1]);
            A[2] = packbf2(C.a[2]); A[3] = packbf2(C.a[3]);
#pragma unroll
            for (int n = 0; n < 4; n++) mma_bf16(hh[n], A, bf[0][0][n]);
            A[0] = packbf2(C.a[4]); A[1] = packbf2(C.a[5]);
            A[2] = packbf2(C.a[6]); A[3] = packbf2(C.a[7]);
#pragma unroll
            for (int n = 0; n < 4; n++) mma_bf16(hh[n], A, bf[0][1][n]);
        }
        layer2(hh, c2, bf[2]);

        // ---- MLP(dists) ----
#pragma unroll
        for (int n = 0; n < 4; n++) {
            hh[n][0] = b1d_lo[n]; hh[n][1] = b1d_hi[n];
            hh[n][2] = b1d_lo[n]; hh[n][3] = b1d_hi[n];
        }
        {
            unsigned A[4];
            A[0] = packbf2(C.d[0]); A[1] = packbf2(C.d[1]);
            A[2] = packbf2(C.d[2]); A[3] = packbf2(C.d[3]);
#pragma unroll
            for (int n = 0; n < 4; n++) mma_bf16(hh[n], A, bf[1][0][n]);
            A[0] = packbf2(C.d[4]); A[1] = packbf2(C.d[5]);
            A[2] = packbf2(C.d[6]); A[3] = packbf2(C.d[7]);
#pragma unroll
            for (int n = 0; n < 4; n++) mma_bf16(hh[n], A, bf[1][1][n]);
        }
        layer2(hh, c2, bf[3]);

        // ---- add attn_bias base, store ----
#pragma unroll
        for (int n = 0; n < 4; n++) {
            float* o = outRow + (size_t)(n * 8 + tq * 2) * PLANE;
            o[j0 + 1 + qid]         = c2[n][0] + C.at0;
            o[PLANE + j0 + 1 + qid] = c2[n][1] + C.at0;
            o[j0 + 9 + qid]         = c2[n][2] + C.at1;
            o[PLANE + j0 + 9 + qid] = c2[n][3] + C.at1;
        }
    }
}

// ---------------------------------------------------------------------------
// Kernel B: border fill (row 0 and column 0): attn + virt
// ---------------------------------------------------------------------------
__global__ __launch_bounds__(256) void border_kernel(
    const float* __restrict__ attn_bias,
    const float* __restrict__ virt,
    float* __restrict__ out)
{
    const int idx = blockIdx.x * 256 + threadIdx.x;
    const int total = NG * HH * 1025;
    if (idx >= total) return;
    const int pos = idx % 1025;
    const int gh  = idx / 1025;
    const int h = gh & 31;
    const int g = gh >> 5;
    const float v = virt[h];
    float* ob = out + ((size_t)(g * HH + h)) * PLANE;
    const float* ab = attn_bias + (size_t)g * PLANE;
    if (pos < NP1) {
        ob[pos] = ab[pos] + v;                        // row 0, all j
    } else {
        const int i = pos - 512;                      // 1..512
        ob[(size_t)i * NP1] = ab[(size_t)i * NP1] + v; // col 0
    }
}

// ---------------------------------------------------------------------------
// Kernel C: edge scatter-add. One warp per edge, lane = head h.
// edge_mask is a jax bool materialized as int32 by the harness.
// ---------------------------------------------------------------------------
__global__ __launch_bounds__(256) void edge_kernel(
    const float* __restrict__ edge_feat,
    const int*   __restrict__ edge_index,
    const int*   __restrict__ edge_mask,
    const int*   __restrict__ num_ligand_atoms,
    const float* __restrict__ struct_emb,
    const float* __restrict__ plip_lig,
    const float* __restrict__ plip_prot,
    const float* __restrict__ plip_inter,
    const float* __restrict__ dist_w1, const float* __restrict__ dist_b1,
    const float* __restrict__ dist_w2, const float* __restrict__ dist_b2,
    float* __restrict__ out)
{
    __shared__ float s_w2[1024];
    __shared__ float s_w1[32], s_b1[32], s_b2[32];
    const int tid = threadIdx.x;
    for (int idx = tid; idx < 1024; idx += 256) s_w2[idx] = dist_w2[idx];
    if (tid < 32) {
        s_w1[tid] = dist_w1[tid];
        s_b1[tid] = dist_b1[tid];
        s_b2[tid] = dist_b2[tid];
    }
    __syncthreads();

    const int warp = tid >> 5;
    const int lane = tid & 31;
    const int eid = blockIdx.x * 8 + warp;     // 0 .. G*E-1 (grid exact)
    if (eid >= NG * NE) return;
    if (edge_mask[eid] == 0) return;           // masked edges contribute 0

    const int g = eid >> 13;                   // / 8192
    const int e = eid & (NE - 1);

    const float4 ef = reinterpret_cast<const float4*>(edge_feat)[eid];
    const int t0 = (int)ef.x;
    const int t1 = (int)ef.y;
    const int t2 = (int)ef.z;
    const float d = ef.w;

    const int src = edge_index[(size_t)g * 2 * NE + e];
    const int tgt = edge_index[(size_t)g * 2 * NE + NE + e];
    int nl = num_ligand_atoms[g];
    nl = nl > 1 ? nl : 1;
    const bool sl = (src > 0) && (src < nl);
    const bool tl = (tgt > 0) && (tgt < nl);

    // distance MLP: scalar -> 32 -> 32 (lane = output h)
    const float hid = fmaxf(fmaf(d, s_w1[lane], s_b1[lane]), 0.f);
    float y = s_b2[lane];
#pragma unroll
    for (int m = 0; m < 32; m++)
        y = fmaf(__shfl_sync(0xffffffffu, hid, m), s_w2[m * 32 + lane], y);

    float sel = 0.f;
    if (t0 <= 1) {
        int si = t0 * 4 + t1 * 2 + t2;
        si = si < 0 ? 0 : (si > 19 ? 19 : si);
        sel = struct_emb[si * 32 + lane];
    } else if (t0 == 5) {
        int pi = t1 < 0 ? 0 : (t1 > 14 ? 14 : t1);
        const float* tab = (sl && tl) ? plip_lig : ((!sl && !tl) ? plip_prot : plip_inter);
        sel = tab[pi * 32 + lane];
    }

    atomicAdd(out + (((size_t)(g * HH + lane)) * NP1 + (src + 1)) * NP1 + (tgt + 1), y + sel);
}

// ---------------------------------------------------------------------------
extern "C" void kernel_launch(void* const* d_in, const int* in_sizes, int n_in,
                              void* d_out, int out_size) {
    const float* edge_feat  = (const float*)d_in[0];
    const int*   edge_index = (const int*)d_in[1];
    const int*   edge_mask  = (const int*)d_in[2];
    const int*   num_lig    = (const int*)d_in[3];
    const float* attn_bias  = (const float*)d_in[4];
    const float* angle      = (const float*)d_in[5];
    const float* dists      = (const float*)d_in[6];
    // d_in[7] node_feat unused (shape only in reference)
    const float* struct_emb = (const float*)d_in[8];
    const float* plip_lig   = (const float*)d_in[9];
    const float* plip_prot  = (const float*)d_in[10];
    const float* plip_inter = (const float*)d_in[11];
    const float* dist_w1 = (const float*)d_in[12];
    const float* dist_b1 = (const float*)d_in[13];
    const float* dist_w2 = (const float*)d_in[14];
    const float* dist_b2 = (const float*)d_in[15];
    const float* ang_w1  = (const float*)d_in[16];
    const float* ang_b1  = (const float*)d_in[17];
    const float* ang_w2  = (const float*)d_in[18];
    const float* ang_b2  = (const float*)d_in[19];
    const float* md_w1   = (const float*)d_in[20];
    const float* md_b1   = (const float*)d_in[21];
    const float* md_w2   = (const float*)d_in[22];
    const float* md_b2   = (const float*)d_in[23];
    const float* virt    = (const float*)d_in[24];
    float* out = (float*)d_out;

    // interior + border overwrite the whole output (disjoint regions),
    // then edge kernel atomically adds on top (stream-ordered).
    interior_kernel<<<NG * NN, 256>>>(attn_bias, angle, dists,
                                      ang_w1, ang_b1, ang_w2, ang_b2,
                                      md_w1, md_b1, md_w2, md_b2, out);
    border_kernel<<<(NG * HH * 1025 + 255) / 256, 256>>>(attn_bias, virt, out);
    edge_kernel<<<NG * NE / 8, 256>>>(edge_feat, edge_index, edge_mask, num_lig,
                                      struct_emb, plip_lig, plip_prot, plip_inter,
                                      dist_w1, dist_b1, dist_w2, dist_b2, out);
}

// round 6
// speedup vs baseline: 1.2399x; 1.0762x over previous
#include <cuda_runtime.h>
#include <cuda_bf16.h>
#include <cstdint>

#define NG 8
#define NE 8192
#define NN 512
#define NP1 513
#define HH 32
#define PLANE (513*513)

// ---------------------------------------------------------------------------
// helpers
// ---------------------------------------------------------------------------
__device__ __forceinline__ unsigned packbf(float lo, float hi) {
    __nv_bfloat162 t = __floats2bfloat162_rn(lo, hi);
    return *reinterpret_cast<unsigned*>(&t);
}
__device__ __forceinline__ unsigned packbf2(float2 v) { return packbf(v.x, v.y); }

__device__ __forceinline__ void mma_bf16(float* c, const unsigned* a, uint2 b) {
    asm volatile(
        "mma.sync.aligned.m16n8k16.row.col.f32.bf16.bf16.f32 "
        "{%0,%1,%2,%3}, {%4,%5,%6,%7}, {%8,%9}, {%0,%1,%2,%3};\n"
        : "+f"(c[0]), "+f"(c[1]), "+f"(c[2]), "+f"(c[3])
        : "r"(a[0]), "r"(a[1]), "r"(a[2]), "r"(a[3]), "r"(b.x), "r"(b.y));
}

// Per-tile prefetched inputs: 8 float2 for angle, 8 for dists, 2 attn scalars.
struct Tile {
    float2 a[8];
    float2 d[8];
    float at0, at1;
};

// Issue all global loads for one 16-point tile (software-pipeline fill stage).
__device__ __forceinline__ void prefetch_tile(Tile& T,
                                              const float* __restrict__ ap,
                                              const float* __restrict__ dp,
                                              const float* __restrict__ attnRow,
                                              int j0, int qid, int tq) {
    const int r0 = qid * 28;
    const int r1 = (qid + 8) * 28;
    const int k0 = tq * 2;        // s=0 cols (k0+8 <= 14, always valid)
    const int k1 = 16 + tq * 2;   // s=1 cols; k1+8 valid only for tq<2
    T.a[0] = __ldcs((const float2*)(ap + r0 + k0));
    T.a[1] = __ldcs((const float2*)(ap + r1 + k0));
    T.a[2] = __ldcs((const float2*)(ap + r0 + k0 + 8));
    T.a[3] = __ldcs((const float2*)(ap + r1 + k0 + 8));
    T.a[4] = __ldcs((const float2*)(ap + r0 + k1));
    T.a[5] = __ldcs((const float2*)(ap + r1 + k1));
    T.d[0] = __ldcs((const float2*)(dp + r0 + k0));
    T.d[1] = __ldcs((const float2*)(dp + r1 + k0));
    T.d[2] = __ldcs((const float2*)(dp + r0 + k0 + 8));
    T.d[3] = __ldcs((const float2*)(dp + r1 + k0 + 8));
    T.d[4] = __ldcs((const float2*)(dp + r0 + k1));
    T.d[5] = __ldcs((const float2*)(dp + r1 + k1));
    if (k1 + 8 < 28) {
        T.a[6] = __ldcs((const float2*)(ap + r0 + k1 + 8));
        T.a[7] = __ldcs((const float2*)(ap + r1 + k1 + 8));
        T.d[6] = __ldcs((const float2*)(dp + r0 + k1 + 8));
        T.d[7] = __ldcs((const float2*)(dp + r1 + k1 + 8));
    } else {
        T.a[6] = T.a[7] = make_float2(0.f, 0.f);
        T.d[6] = T.d[7] = make_float2(0.f, 0.f);
    }
    T.at0 = __ldg(attnRow + j0 + 1 + qid);
    T.at1 = __ldg(attnRow + j0 + 9 + qid);
}

// ---------------------------------------------------------------------------
// Kernel A: interior fill  out[g,h,i,j] for i,j in [1,512]
// block = 256 threads (8 warps) per (g,i) row; each warp 4 tiles of 16 j's.
// Weight/bias MMA fragments live in SMEM in lane-major layout so registers
// stay <=128 -> 2 CTAs/SM (16 warps) for latency hiding.
// ---------------------------------------------------------------------------
__global__ __launch_bounds__(256, 2) void interior_kernel(
    const float* __restrict__ attn_bias,
    const float* __restrict__ angle,
    const float* __restrict__ dists,
    const float* __restrict__ ang_w1, const float* __restrict__ ang_b1,
    const float* __restrict__ ang_w2, const float* __restrict__ ang_b2,
    const float* __restrict__ md_w1,  const float* __restrict__ md_b1,
    const float* __restrict__ md_w2,  const float* __restrict__ md_b2,
    float* __restrict__ out)
{
    // [m*8 + s*4 + n][lane] -> {word0, word1} of the B fragment
    __shared__ uint2  wfrag[32][32];
    // [mat][n][lane] -> {lo, hi} bias pair (mat: 0=ang_b1, 1=md_b1, 2=b2 sum)
    __shared__ float2 bfr[3][4][32];

    const int tid = threadIdx.x;

    // Build B fragments directly from the (tiny, L2-resident) weight tensors.
    for (int e = tid; e < 1024; e += 256) {
        const int p = e >> 5, ln = e & 31;
        const int m = p >> 3, s = (p >> 2) & 1, n = p & 3;
        const int q = ln >> 2, tq4 = ln & 3;
        const int r0 = s * 16 + tq4 * 2;
        const int c  = n * 8 + q;
        const float* w = (m == 0) ? ang_w1 : (m == 1) ? md_w1 : (m == 2) ? ang_w2 : md_w2;
        const bool pad = (m < 2);   // w1 matrices: rows 28..31 are zero
        float v00 = (pad && r0     >= 28) ? 0.f : w[(r0)     * 32 + c];
        float v01 = (pad && r0 + 1 >= 28) ? 0.f : w[(r0 + 1) * 32 + c];
        float v10 = (pad && r0 + 8 >= 28) ? 0.f : w[(r0 + 8) * 32 + c];
        float v11 = (pad && r0 + 9 >= 28) ? 0.f : w[(r0 + 9) * 32 + c];
        wfrag[p][ln] = make_uint2(packbf(v00, v01), packbf(v10, v11));
    }
    for (int e = tid; e < 384; e += 256) {
        const int mat = e >> 7, rem = e & 127, n = rem >> 5, ln = rem & 31;
        const int i2 = n * 8 + (ln & 3) * 2;
        float lo, hi;
        if (mat == 0)      { lo = ang_b1[i2];              hi = ang_b1[i2 + 1]; }
        else if (mat == 1) { lo = md_b1[i2];               hi = md_b1[i2 + 1]; }
        else               { lo = ang_b2[i2] + md_b2[i2];  hi = ang_b2[i2 + 1] + md_b2[i2 + 1]; }
        bfr[mat][n][ln] = make_float2(lo, hi);
    }
    __syncthreads();

    const int lane = tid & 31;
    const int warp = tid >> 5;
    const int qid  = lane >> 2;   // 0..7
    const int tq   = lane & 3;    // 0..3

    const int bid = blockIdx.x;
    const int g = bid >> 9;           // / 512
    const int i = (bid & 511) + 1;    // out row 1..512
    const size_t rowp = (size_t)(g * NN + (i - 1)) * NN * 28;
    const float* angRow  = angle + rowp;
    const float* dstRow  = dists + rowp;
    const float* attnRow = attn_bias + ((size_t)g * NP1 + i) * NP1;
    float* outRow = out + (size_t)g * HH * PLANE + (size_t)i * NP1;

    Tile T[2];
    prefetch_tile(T[0], angRow + (size_t)(warp * 16) * 28,
                        dstRow + (size_t)(warp * 16) * 28, attnRow,
                        warp * 16, qid, tq);

#pragma unroll
    for (int it = 0; it < 4; it++) {
        const int cur = it & 1;
        const int t  = warp + it * 8;
        const int j0 = t * 16;

        if (it < 3) {
            const int jn = (t + 8) * 16;
            prefetch_tile(T[cur ^ 1], angRow + (size_t)jn * 28,
                                      dstRow + (size_t)jn * 28, attnRow,
                                      jn, qid, tq);
        }

        const Tile& C = T[cur];

        float c2[4][4];
#pragma unroll
        for (int n = 0; n < 4; n++) {
            const float2 b = bfr[2][n][lane];
            c2[n][0] = b.x; c2[n][1] = b.y; c2[n][2] = b.x; c2[n][3] = b.y;
        }

        float hh[4][4];
        unsigned A[4];

        // ---- MLP(angle), layer 1 ----
#pragma unroll
        for (int n = 0; n < 4; n++) {
            const float2 b = bfr[0][n][lane];
            hh[n][0] = b.x; hh[n][1] = b.y; hh[n][2] = b.x; hh[n][3] = b.y;
        }
        A[0] = packbf2(C.a[0]); A[1] = packbf2(C.a[1]);
        A[2] = packbf2(C.a[2]); A[3] = packbf2(C.a[3]);
#pragma unroll
        for (int n = 0; n < 4; n++) mma_bf16(hh[n], A, wfrag[0 * 8 + 0 * 4 + n][lane]);
        A[0] = packbf2(C.a[4]); A[1] = packbf2(C.a[5]);
        A[2] = packbf2(C.a[6]); A[3] = packbf2(C.a[7]);
#pragma unroll
        for (int n = 0; n < 4; n++) mma_bf16(hh[n], A, wfrag[0 * 8 + 1 * 4 + n][lane]);

        // ---- relu -> layer 2 (ang_w2 = m2) ----
#pragma unroll
        for (int s = 0; s < 2; s++) {
            A[0] = packbf(fmaxf(hh[2*s][0], 0.f), fmaxf(hh[2*s][1], 0.f));
            A[1] = packbf(fmaxf(hh[2*s][2], 0.f), fmaxf(hh[2*s][3], 0.f));
            A[2] = packbf(fmaxf(hh[2*s+1][0], 0.f), fmaxf(hh[2*s+1][1], 0.f));
            A[3] = packbf(fmaxf(hh[2*s+1][2], 0.f), fmaxf(hh[2*s+1][3], 0.f));
#pragma unroll
            for (int n = 0; n < 4; n++) mma_bf16(c2[n], A, wfrag[2 * 8 + s * 4 + n][lane]);
        }

        // ---- MLP(dists), layer 1 ----
#pragma unroll
        for (int n = 0; n < 4; n++) {
            const float2 b = bfr[1][n][lane];
            hh[n][0] = b.x; hh[n][1] = b.y; hh[n][2] = b.x; hh[n][3] = b.y;
        }
        A[0] = packbf2(C.d[0]); A[1] = packbf2(C.d[1]);
        A[2] = packbf2(C.d[2]); A[3] = packbf2(C.d[3]);
#pragma unroll
        for (int n = 0; n < 4; n++) mma_bf16(hh[n], A, wfrag[1 * 8 + 0 * 4 + n][lane]);
        A[0] = packbf2(C.d[4]); A[1] = packbf2(C.d[5]);
        A[2] = packbf2(C.d[6]); A[3] = packbf2(C.d[7]);
#pragma unroll
        for (int n = 0; n < 4; n++) mma_bf16(hh[n], A, wfrag[1 * 8 + 1 * 4 + n][lane]);

        // ---- relu -> layer 2 (md_w2 = m3) ----
#pragma unroll
        for (int s = 0; s < 2; s++) {
            A[0] = packbf(fmaxf(hh[2*s][0], 0.f), fmaxf(hh[2*s][1], 0.f));
            A[1] = packbf(fmaxf(hh[2*s][2], 0.f), fmaxf(hh[2*s][3], 0.f));
            A[2] = packbf(fmaxf(hh[2*s+1][0], 0.f), fmaxf(hh[2*s+1][1], 0.f));
            A[3] = packbf(fmaxf(hh[2*s+1][2], 0.f), fmaxf(hh[2*s+1][3], 0.f));
#pragma unroll
            for (int n = 0; n < 4; n++) mma_bf16(c2[n], A, wfrag[3 * 8 + s * 4 + n][lane]);
        }

        // ---- add attn_bias base, store ----
#pragma unroll
        for (int n = 0; n < 4; n++) {
            float* o = outRow + (size_t)(n * 8 + tq * 2) * PLANE;
            o[j0 + 1 + qid]         = c2[n][0] + C.at0;
            o[PLANE + j0 + 1 + qid] = c2[n][1] + C.at0;
            o[j0 + 9 + qid]         = c2[n][2] + C.at1;
            o[PLANE + j0 + 9 + qid] = c2[n][3] + C.at1;
        }
    }
}

// ---------------------------------------------------------------------------
// Kernel B: border fill (row 0 and column 0): attn + virt
// ---------------------------------------------------------------------------
__global__ __launch_bounds__(256) void border_kernel(
    const float* __restrict__ attn_bias,
    const float* __restrict__ virt,
    float* __restrict__ out)
{
    const int idx = blockIdx.x * 256 + threadIdx.x;
    const int total = NG * HH * 1025;
    if (idx >= total) return;
    const int pos = idx % 1025;
    const int gh  = idx / 1025;
    const int h = gh & 31;
    const int g = gh >> 5;
    const float v = virt[h];
    float* ob = out + ((size_t)(g * HH + h)) * PLANE;
    const float* ab = attn_bias + (size_t)g * PLANE;
    if (pos < NP1) {
        ob[pos] = ab[pos] + v;                        // row 0, all j
    } else {
        const int i = pos - 512;                      // 1..512
        ob[(size_t)i * NP1] = ab[(size_t)i * NP1] + v; // col 0
    }
}

// ---------------------------------------------------------------------------
// Kernel C: edge scatter-add. One warp per edge, lane = head h.
// edge_mask is a jax bool materialized as int32 by the harness.
// ---------------------------------------------------------------------------
__global__ __launch_bounds__(256) void edge_kernel(
    const float* __restrict__ edge_feat,
    const int*   __restrict__ edge_index,
    const int*   __restrict__ edge_mask,
    const int*   __restrict__ num_ligand_atoms,
    const float* __restrict__ struct_emb,
    const float* __restrict__ plip_lig,
    const float* __restrict__ plip_prot,
    const float* __restrict__ plip_inter,
    const float* __restrict__ dist_w1, const float* __restrict__ dist_b1,
    const float* __restrict__ dist_w2, const float* __restrict__ dist_b2,
    float* __restrict__ out)
{
    __shared__ float s_w2[1024];
    __shared__ float s_w1[32], s_b1[32], s_b2[32];
    const int tid = threadIdx.x;
    for (int idx = tid; idx < 1024; idx += 256) s_w2[idx] = dist_w2[idx];
    if (tid < 32) {
        s_w1[tid] = dist_w1[tid];
        s_b1[tid] = dist_b1[tid];
        s_b2[tid] = dist_b2[tid];
    }
    __syncthreads();

    const int warp = tid >> 5;
    const int lane = tid & 31;
    const int eid = blockIdx.x * 8 + warp;     // 0 .. G*E-1 (grid exact)
    if (eid >= NG * NE) return;
    if (edge_mask[eid] == 0) return;           // masked edges contribute 0

    const int g = eid >> 13;                   // / 8192
    const int e = eid & (NE - 1);

    const float4 ef = reinterpret_cast<const float4*>(edge_feat)[eid];
    const int t0 = (int)ef.x;
    const int t1 = (int)ef.y;
    const int t2 = (int)ef.z;
    const float d = ef.w;

    const int src = edge_index[(size_t)g * 2 * NE + e];
    const int tgt = edge_index[(size_t)g * 2 * NE + NE + e];
    int nl = num_ligand_atoms[g];
    nl = nl > 1 ? nl : 1;
    const bool sl = (src > 0) && (src < nl);
    const bool tl = (tgt > 0) && (tgt < nl);

    // distance MLP: scalar -> 32 -> 32 (lane = output h)
    const float hid = fmaxf(fmaf(d, s_w1[lane], s_b1[lane]), 0.f);
    float y = s_b2[lane];
#pragma unroll
    for (int m = 0; m < 32; m++)
        y = fmaf(__shfl_sync(0xffffffffu, hid, m), s_w2[m * 32 + lane], y);

    float sel = 0.f;
    if (t0 <= 1) {
        int si = t0 * 4 + t1 * 2 + t2;
        si = si < 0 ? 0 : (si > 19 ? 19 : si);
        sel = struct_emb[si * 32 + lane];
    } else if (t0 == 5) {
        int pi = t1 < 0 ? 0 : (t1 > 14 ? 14 : t1);
        const float* tab = (sl && tl) ? plip_lig : ((!sl && !tl) ? plip_prot : plip_inter);
        sel = tab[pi * 32 + lane];
    }

    atomicAdd(out + (((size_t)(g * HH + lane)) * NP1 + (src + 1)) * NP1 + (tgt + 1), y + sel);
}

// ---------------------------------------------------------------------------
extern "C" void kernel_launch(void* const* d_in, const int* in_sizes, int n_in,
                              void* d_out, int out_size) {
    const float* edge_feat  = (const float*)d_in[0];
    const int*   edge_index = (const int*)d_in[1];
    const int*   edge_mask  = (const int*)d_in[2];
    const int*   num_lig    = (const int*)d_in[3];
    const float* attn_bias  = (const float*)d_in[4];
    const float* angle      = (const float*)d_in[5];
    const float* dists      = (const float*)d_in[6];
    // d_in[7] node_feat unused (shape only in reference)
    const float* struct_emb = (const float*)d_in[8];
    const float* plip_lig   = (const float*)d_in[9];
    const float* plip_prot  = (const float*)d_in[10];
    const float* plip_inter = (const float*)d_in[11];
    const float* dist_w1 = (const float*)d_in[12];
    const float* dist_b1 = (const float*)d_in[13];
    const float* dist_w2 = (const float*)d_in[14];
    const float* dist_b2 = (const float*)d_in[15];
    const float* ang_w1  = (const float*)d_in[16];
    const float* ang_b1  = (const float*)d_in[17];
    const float* ang_w2  = (const float*)d_in[18];
    const float* ang_b2  = (const float*)d_in[19];
    const float* md_w1   = (const float*)d_in[20];
    const float* md_b1   = (const float*)d_in[21];
    const float* md_w2   = (const float*)d_in[22];
    const float* md_b2   = (const float*)d_in[23];
    const float* virt    = (const float*)d_in[24];
    float* out = (float*)d_out;

    // interior + border overwrite the whole output (disjoint regions),
    // then edge kernel atomically adds on top (stream-ordered).
    interior_kernel<<<NG * NN, 256>>>(attn_bias, angle, dists,
                                      ang_w1, ang_b1, ang_w2, ang_b2,
                                      md_w1, md_b1, md_w2, md_b2, out);
    border_kernel<<<(NG * HH * 1025 + 255) / 256, 256>>>(attn_bias, virt, out);
    edge_kernel<<<NG * NE / 8, 256>>>(edge_feat, edge_index, edge_mask, num_lig,
                                      struct_emb, plip_lig, plip_prot, plip_inter,
                                      dist_w1, dist_b1, dist_w2, dist_b2, out);
}